// round 12
// baseline (speedup 1.0000x reference)
#include <cuda_runtime.h>
#include <cuda_fp16.h>
#include <cstdint>

#define BB   2
#define AA   512
#define TT   512
#define NF   128
#define NRBF 25
#define TILT 64
#define NTIL (TT / TILT)   // 8

#define RSH 40    // sRbf row stride (halves)
#define HSH 136   // sH   row stride (halves)
#define WSH 140   // sW   row stride (halves)
#define WBUF (TILT * WSH)

__device__ __half2  g_y2[BB * AA * NF / 2];
__device__ uint32_t g_w1ph[2 * 32 * 32];
__device__ uint32_t g_w2ph[8 * 32 * 32];

// fp32 shifted softplus (tiny f2out epilogue only)
__device__ __forceinline__ float ssp(float v) {
    const float m = fmaxf(v, 0.0f);
    const float u = __expf(-fabsf(v));
    const float x = fmaf(2.0f, u, -1.0f);
    float p = -0.00342936f;
    p = fmaf(p, x, 0.01337449f);
    p = fmaf(p, x, -0.05542695f);
    p = fmaf(p, x, 0.33307613f);
    p = fmaf(p, x, -0.28768922f);   // 0.40545796 - ln2
    return m + p;
}

// fully-packed half2 ssp: x = 2*exp(-|v|)-1 = ex2(1 - |v|*log2e) - 1,
// then deg-4 fp16 poly for ln(1+u)-ln2. ~12 instructions per 2 values.
__device__ __forceinline__ __half2 ssp2(float c0, float c1) {
    const __half2 v  = __floats2half2_rn(c0, c1);
    const __half2 av = __habs2(v);
    const __half2 arg = __hfma2(av, __float2half2_rn(-1.44269504f),
                                __float2half2_rn(1.0f));
    __half2 e;
    asm("ex2.approx.f16x2 %0, %1;"
        : "=r"(*(uint32_t*)&e) : "r"(*(const uint32_t*)&arg));
    const __half2 x = __hadd2(e, __float2half2_rn(-1.0f));
    __half2 p = __float2half2_rn(-0.00342936f);
    p = __hfma2(p, x, __float2half2_rn(0.01337449f));
    p = __hfma2(p, x, __float2half2_rn(-0.05542695f));
    p = __hfma2(p, x, __float2half2_rn(0.33307613f));
    p = __hfma2(p, x, __float2half2_rn(-0.28768922f));
    const __half2 m = __hmax2(v, __float2half2_rn(0.0f));
    return __hadd2(m, p);
}
__device__ __forceinline__ uint32_t smem_u32(const void* p) {
    uint32_t a;
    asm("{ .reg .u64 t; cvta.to.shared.u64 t, %1; cvt.u32.u64 %0, t; }"
        : "=r"(a) : "l"(p));
    return a;
}
__device__ __forceinline__ void mma16(float* c, const uint32_t* a,
                                      uint32_t b0, uint32_t b1) {
    asm volatile(
        "mma.sync.aligned.m16n8k16.row.col.f32.f16.f16.f32 "
        "{%0,%1,%2,%3}, {%4,%5,%6,%7}, {%8,%9}, {%0,%1,%2,%3};"
        : "+f"(c[0]), "+f"(c[1]), "+f"(c[2]), "+f"(c[3])
        : "r"(a[0]), "r"(a[1]), "r"(a[2]), "r"(a[3]), "r"(b0), "r"(b1));
}
__device__ __forceinline__ void ldmat4(uint32_t* r, uint32_t addr) {
    asm volatile(
        "ldmatrix.sync.aligned.m8n8.x4.shared.b16 {%0,%1,%2,%3}, [%4];"
        : "=r"(r[0]), "=r"(r[1]), "=r"(r[2]), "=r"(r[3]) : "r"(addr));
}
__device__ __forceinline__ uint32_t packh2(float lo, float hi) {
    __half2 h = __floats2half2_rn(lo, hi);
    return *reinterpret_cast<uint32_t*>(&h);
}

// ---------------------------------------------------------------------------
// fused prep + in2f (y stored fp16); bf1 folded into k=25 of w1 table
// ---------------------------------------------------------------------------
__global__ void prep_in2f_kernel(const float* __restrict__ x,
                                 const float* __restrict__ Win,
                                 const float* __restrict__ Wf1,
                                 const float* __restrict__ Wf2,
                                 const float* __restrict__ bf1) {
    if (blockIdx.x < 256) {
        __shared__ float xs[4][NF];
        const int row4 = blockIdx.x * 4;
        for (int i = threadIdx.x; i < 4 * NF; i += 256)
            xs[i >> 7][i & 127] = x[(row4 + (i >> 7)) * NF + (i & 127)];
        __syncthreads();
        const int sub = threadIdx.x >> 6;
        const int f0 = (threadIdx.x & 63) * 2;
        float a0 = 0.0f, a1 = 0.0f;
#pragma unroll 8
        for (int i = 0; i < NF; ++i) {
            a0 += xs[sub][i] * Win[i * NF + f0];
            a1 += xs[sub][i] * Win[i * NF + f0 + 1];
        }
        g_y2[((row4 + sub) * NF + f0) >> 1] = __floats2half2_rn(a0, a1);
    } else {
        const int idx = (blockIdx.x - 256) * 256 + threadIdx.x;
        if (idx < 2048) {
            const int ks = idx >> 10, rem = idx & 1023;
            const int lane = rem >> 5, i = rem & 31;
            const int j = i >> 1, r = i & 1;
            const int n = j * 8 + (lane >> 2);
            const int k0 = ks * 16 + r * 8 + (lane & 3) * 2;
            const float v0 = (k0 < NRBF) ? Wf1[k0 * NF + n]
                           : (k0 == NRBF ? bf1[n] : 0.0f);
            const float v1 = (k0 + 1 < NRBF) ? Wf1[(k0 + 1) * NF + n]
                           : (k0 + 1 == NRBF ? bf1[n] : 0.0f);
            const int off = (ks * 32 + lane) * 32 +
                            ((((i >> 2) ^ (lane & 7)) << 2) + (i & 3));
            g_w1ph[off] = packh2(v0, v1);
        } else if (idx < 2048 + 8192) {
            const int t = idx - 2048;
            const int ks = t >> 10, rem = t & 1023;
            const int lane = rem >> 5, i = rem & 31;
            const int j = i >> 1, r = i & 1;
            const int n = j * 8 + (lane >> 2);
            const int k0 = ks * 16 + r * 8 + (lane & 3) * 2;
            const int off = (ks * 32 + lane) * 32 +
                            ((((i >> 2) ^ (lane & 7)) << 2) + (i & 3));
            g_w2ph[off] = packh2(Wf2[k0 * NF + n], Wf2[(k0 + 1) * NF + n]);
        }
    }
}

// ---------------------------------------------------------------------------
// SMEM layout (bytes)
// ---------------------------------------------------------------------------
#define OFF_H     0          // 17408
#define OFF_W2P   17408      // 32768
#define OFF_RBF   50176      // 5120
#define OFF_W     55296      // 35840 (fp16 W double buffer)
#define OFF_BF2   91136      // 512
#define OFF_MASK  91648      // 512
#define OFF_NJ    92160      // 512
#define OFF_NK    92672      // 512
#define SMEM_BYTES 93184

#define NTHREADS 256

__global__ __launch_bounds__(NTHREADS, 2)
void cfconv_mma(const float* __restrict__ r_ij,
                const float* __restrict__ pmask,
                const float* __restrict__ bf2,
                const float* __restrict__ Wout, const float* __restrict__ bout,
                const int* __restrict__ nj, const int* __restrict__ nk,
                float* __restrict__ out) {
    extern __shared__ __align__(16) char smem[];
    __half*   sHh   = (__half*)(smem + OFF_H);
    uint32_t* sW2p  = (uint32_t*)(smem + OFF_W2P);
    __half*   sRbfH = (__half*)(smem + OFF_RBF);
    __half*   sWh   = (__half*)(smem + OFF_W);
    float* sBf2  = (float*)(smem + OFF_BF2);
    float* sMask = (float*)(smem + OFF_MASK);
    int*   sNj   = (int*)(smem + OFF_NJ);
    int*   sNk   = (int*)(smem + OFF_NK);
    float* sPart = (float*)(smem + OFF_W);
    float* sY    = (float*)(smem + OFF_W + 4096);
    float* sRed  = (float*)(smem + OFF_W + 4608);

    const int tid  = threadIdx.x;
    const int wid  = tid >> 5;
    const int lane = tid & 31;
    const int gid  = lane >> 2;
    const int l4   = lane & 3;
    const int wm   = wid >> 2;
    const int wn   = wid & 3;
    const int mbase = wm * 32;
    const int nb4   = wn * 2;
    const int f4    = lane * 4;
    const int a = blockIdx.x, b = blockIdx.y;
    const int ba = b * AA + a;
    const __half* Yb = (const __half*)g_y2 + (long)b * AA * NF;

    // division-free staging map: thread -> (t row, 7-col slice)
    const int st_t  = tid >> 2;          // 0..63
    const int st_r0 = (tid & 3) * 7;     // 0,7,14,21

    const int lrow  = (lane & 7) + ((lane >> 3) & 1) * 8;
    const int lkh   = ((lane >> 4) & 1) * 8;
    uint32_t addrR[2], addrH[2];
#pragma unroll
    for (int mt = 0; mt < 2; ++mt) {
        addrR[mt] = smem_u32(sRbfH + (mbase + mt * 16 + lrow) * RSH + lkh);
        addrH[mt] = smem_u32(sHh + (mbase + mt * 16 + lrow) * HSH + lkh);
    }

    // ---- prologue ----
    {
        const uint4* src = (const uint4*)g_w2ph;
        uint4* dst = (uint4*)sW2p;
        for (int i = tid; i < 2048; i += NTHREADS) dst[i] = src[i];
    }
    {
        uint32_t* z = (uint32_t*)sRbfH;
        for (int i = tid; i < (TILT * RSH) / 2; i += NTHREADS) z[i] = 0u;
    }
    if (tid < NF) sBf2[tid] = bf2[tid];

    uint32_t w1b[2][8];
#pragma unroll
    for (int ks = 0; ks < 2; ++ks) {
        const uint4* rowp = (const uint4*)g_w1ph + (ks * 32 + lane) * 8;
        uint4 q0 = __ldg(rowp + (nb4 ^ (lane & 7)));
        uint4 q1 = __ldg(rowp + ((nb4 + 1) ^ (lane & 7)));
        w1b[ks][0] = q0.x; w1b[ks][1] = q0.y; w1b[ks][2] = q0.z; w1b[ks][3] = q0.w;
        w1b[ks][4] = q1.x; w1b[ks][5] = q1.y; w1b[ks][6] = q1.z; w1b[ks][7] = q1.w;
    }
    __syncthreads();      // rbf zeros visible
    {   // bias column (k=25 of rbf = 1.0) + stage tile 0 (div-free map)
        if (tid < TILT) sRbfH[tid * RSH + NRBF] = __float2half_rn(1.0f);
        const float* rsrc = r_ij + (long)ba * TT * NRBF + st_t * NRBF;
#pragma unroll
        for (int q = 0; q < 7; ++q) {
            const int r = st_r0 + q;
            if (r < NRBF) sRbfH[st_t * RSH + r] = __float2half_rn(rsrc[r]);
        }
        if (tid < TILT) {
            const long p = (long)ba * TT + tid;
            sMask[tid] = pmask[p];
            sNj[tid] = nj[p];
            sNk[tid] = nk[p];
        }
    }
    __syncthreads();

    float4 acc0 = make_float4(0.f, 0.f, 0.f, 0.f);
    float4 acc1 = make_float4(0.f, 0.f, 0.f, 0.f);

    for (int tile = 0; tile < NTIL; ++tile) {
        const int cur = tile & 1;
        const int nxt = cur ^ 1;

        float C[2][4][4];
#pragma unroll
        for (int mt = 0; mt < 2; ++mt)
#pragma unroll
            for (int j = 0; j < 4; ++j)
#pragma unroll
                for (int q = 0; q < 4; ++q) C[mt][j][q] = 0.0f;

        // ---- GEMM1 (bf1 folded via k=25 bias column) ----
#pragma unroll
        for (int ks = 0; ks < 2; ++ks) {
            uint32_t A[2][4];
            ldmat4(A[0], addrR[0] + ks * 32);
            ldmat4(A[1], addrR[1] + ks * 32);
#pragma unroll
            for (int mt = 0; mt < 2; ++mt)
#pragma unroll
                for (int j = 0; j < 4; ++j)
                    mma16(C[mt][j], A[mt], w1b[ks][2 * j], w1b[ks][2 * j + 1]);
        }

        // ---- ssp (packed half2, ex2.f16x2) -> sH ----
#pragma unroll
        for (int mt = 0; mt < 2; ++mt)
#pragma unroll
            for (int j = 0; j < 4; ++j) {
                const int f0 = wn * 32 + j * 8 + l4 * 2;
                const int r0 = mbase + mt * 16 + gid;
                *(__half2*)(sHh + r0 * HSH + f0) = ssp2(C[mt][j][0], C[mt][j][1]);
                *(__half2*)(sHh + (r0 + 8) * HSH + f0) = ssp2(C[mt][j][2], C[mt][j][3]);
            }

        // ---- prefetch next tile into registers (div-free map) ----
        float rstg[7];
        float stg_mk = 0.0f; int stg_j = 0, stg_k = 0;
        if (tile < NTIL - 1) {
            const float* rnext = r_ij + ((long)ba * TT + (tile + 1) * TILT) * NRBF
                                 + st_t * NRBF;
#pragma unroll
            for (int q = 0; q < 7; ++q) {
                const int r = st_r0 + q;
                if (r < NRBF) rstg[q] = rnext[r];
            }
            if (tid < TILT) {
                const long p = (long)ba * TT + (tile + 1) * TILT + tid;
                stg_mk = pmask[p];
                stg_j = nj[p];
                stg_k = nk[p];
            }
        }
        __syncthreads();   // sync1: sH visible

        // ---- GEMM2 ----
#pragma unroll
        for (int mt = 0; mt < 2; ++mt)
#pragma unroll
            for (int j = 0; j < 4; ++j)
#pragma unroll
                for (int q = 0; q < 4; ++q) C[mt][j][q] = 0.0f;
#pragma unroll
        for (int ks = 0; ks < 8; ++ks) {
            uint32_t A[2][4];
            ldmat4(A[0], addrH[0] + ks * 32);
            ldmat4(A[1], addrH[1] + ks * 32);
            const uint4* rowp = (const uint4*)sW2p + (ks * 32 + lane) * 8;
            uint4 q0 = rowp[nb4 ^ (lane & 7)];
            uint4 q1 = rowp[(nb4 + 1) ^ (lane & 7)];
            uint32_t bu[8] = {q0.x, q0.y, q0.z, q0.w, q1.x, q1.y, q1.z, q1.w};
#pragma unroll
            for (int mt = 0; mt < 2; ++mt)
#pragma unroll
                for (int j = 0; j < 4; ++j)
                    mma16(C[mt][j], A[mt], bu[2 * j], bu[2 * j + 1]);
        }

        // ---- store (C + bf2) * mask as fp16 -> W buffer[cur] ----
        {
            __half* wb = sWh + cur * WBUF;
#pragma unroll
            for (int mt = 0; mt < 2; ++mt) {
                const int t0 = mbase + mt * 16 + gid;
                const float m0 = sMask[cur * TILT + t0];
                const float m1 = sMask[cur * TILT + t0 + 8];
#pragma unroll
                for (int j = 0; j < 4; ++j) {
                    const int f0 = wn * 32 + j * 8 + l4 * 2;
                    const float2 b2 = *(const float2*)(sBf2 + f0);
                    *(__half2*)(wb + t0 * WSH + f0) =
                        __floats2half2_rn((C[mt][j][0] + b2.x) * m0,
                                          (C[mt][j][1] + b2.y) * m0);
                    *(__half2*)(wb + (t0 + 8) * WSH + f0) =
                        __floats2half2_rn((C[mt][j][2] + b2.x) * m1,
                                          (C[mt][j][3] + b2.y) * m1);
                }
            }
        }

        // ---- store staged tile (div-free map) ----
        if (tile < NTIL - 1) {
#pragma unroll
            for (int q = 0; q < 7; ++q) {
                const int r = st_r0 + q;
                if (r < NRBF) sRbfH[st_t * RSH + r] = __float2half_rn(rstg[q]);
            }
            if (tid < TILT) {
                sMask[nxt * TILT + tid] = stg_mk;
                sNj[nxt * TILT + tid] = stg_j;
                sNk[nxt * TILT + tid] = stg_k;
            }
        }
        __syncthreads();   // sync2

        // ---- row-coalesced epilogue, fp16 y, 2 acc chains ----
        {
            const __half* wb = sWh + cur * WBUF;
#pragma unroll
            for (int r = 0; r < 8; r += 2) {
#pragma unroll
                for (int h = 0; h < 2; ++h) {
                    const int t = wid * 8 + r + h;
                    const uint2 yju = *(const uint2*)(Yb + sNj[cur * TILT + t] * NF + f4);
                    const uint2 yku = *(const uint2*)(Yb + sNk[cur * TILT + t] * NF + f4);
                    const float2 ja = __half22float2(*(const __half2*)&yju.x);
                    const float2 jb = __half22float2(*(const __half2*)&yju.y);
                    const float2 ka = __half22float2(*(const __half2*)&yku.x);
                    const float2 kb = __half22float2(*(const __half2*)&yku.y);
                    const uint2 wu = *(const uint2*)(wb + t * WSH + f4);
                    const float2 wlo = __half22float2(*(const __half2*)&wu.x);
                    const float2 whi = __half22float2(*(const __half2*)&wu.y);
                    float4& av = h ? acc1 : acc0;
                    av.x = fmaf(wlo.x, ja.x * ka.x, av.x);
                    av.y = fmaf(wlo.y, ja.y * ka.y, av.y);
                    av.z = fmaf(whi.x, jb.x * kb.x, av.z);
                    av.w = fmaf(whi.y, jb.y * kb.y, av.w);
                }
            }
        }
    }

    __syncthreads();
    // ---- cross-warp reduce ----
    {
        float4 accv = make_float4(acc0.x + acc1.x, acc0.y + acc1.y,
                                  acc0.z + acc1.z, acc0.w + acc1.w);
        *(float4*)(sPart + wid * NF + f4) = accv;
    }
    __syncthreads();
    if (tid < NF) {
        float s = 0.0f;
#pragma unroll
        for (int w = 0; w < 8; ++w) s += sPart[w * NF + tid];
        sY[tid] = s;
    }
    __syncthreads();

    // ---- f2out ----
    {
        const int o = tid & 127;
        const int q = tid >> 7;
        float s = 0.0f;
        const float* Wp = Wout + q * 64 * NF + o;
#pragma unroll 8
        for (int f = 0; f < 64; ++f) s += sY[q * 64 + f] * Wp[f * NF];
        sRed[q * NF + o] = s;
    }
    __syncthreads();
    if (tid < NF)
        out[(long)ba * NF + tid] = ssp(sRed[tid] + sRed[NF + tid] + bout[tid]);
}

// ---------------------------------------------------------------------------
extern "C" void kernel_launch(void* const* d_in, const int* in_sizes, int n_in,
                              void* d_out, int out_size) {
    const float* x    = (const float*)d_in[0];
    const float* r_ij = (const float*)d_in[1];
    const float* mask = (const float*)d_in[2];
    const float* Wf1  = (const float*)d_in[3];
    const float* bf1  = (const float*)d_in[4];
    const float* Wf2  = (const float*)d_in[5];
    const float* bf2  = (const float*)d_in[6];
    const float* Win  = (const float*)d_in[7];
    const float* Wout = (const float*)d_in[8];
    const float* bout = (const float*)d_in[9];
    const int*   nj   = (const int*)d_in[10];
    const int*   nk   = (const int*)d_in[11];
    float* out = (float*)d_out;

    prep_in2f_kernel<<<296, 256>>>(x, Win, Wf1, Wf2, bf1);

    cudaFuncSetAttribute(cfconv_mma,
                         cudaFuncAttributeMaxDynamicSharedMemorySize, SMEM_BYTES);
    dim3 grid(AA, BB);
    cfconv_mma<<<grid, NTHREADS, SMEM_BYTES>>>(r_ij, mask, bf2,
                                               Wout, bout, nj, nk, out);
}

// round 13
// speedup vs baseline: 1.0059x; 1.0059x over previous
#include <cuda_runtime.h>
#include <cuda_fp16.h>
#include <cstdint>

#define BB   2
#define AA   512
#define TT   512
#define NF   128
#define NRBF 25
#define TILT 64
#define NTIL (TT / TILT)   // 8

#define RSH 40    // sRbf row stride (halves)
#define HSH 136   // sH   row stride (halves)
#define WSH 140   // sW   row stride (halves)
#define WBUF (TILT * WSH)

__device__ __half2  g_y2[BB * AA * NF / 2];
__device__ uint32_t g_w1ph[2 * 32 * 32];   // 8KB
__device__ uint32_t g_w2ph[8 * 32 * 32];   // 32KB

// fp32 shifted softplus (deg-4 economized poly, |err|~6e-5)
__device__ __forceinline__ float ssp(float v) {
    const float m = fmaxf(v, 0.0f);
    const float u = __expf(-fabsf(v));
    const float x = fmaf(2.0f, u, -1.0f);
    float p = -0.00342936f;
    p = fmaf(p, x, 0.01337449f);
    p = fmaf(p, x, -0.05542695f);
    p = fmaf(p, x, 0.33307613f);
    p = fmaf(p, x, -0.28768922f);   // 0.40545796 - ln2
    return m + p;
}
// pairwise ssp: fp32 math, single fp16 rounding at the pack
__device__ __forceinline__ __half2 ssp2(float c0, float c1) {
    return __floats2half2_rn(ssp(c0), ssp(c1));
}
__device__ __forceinline__ uint32_t smem_u32(const void* p) {
    uint32_t a;
    asm("{ .reg .u64 t; cvta.to.shared.u64 t, %1; cvt.u32.u64 %0, t; }"
        : "=r"(a) : "l"(p));
    return a;
}
__device__ __forceinline__ void mma16(float* c, const uint32_t* a,
                                      uint32_t b0, uint32_t b1) {
    asm volatile(
        "mma.sync.aligned.m16n8k16.row.col.f32.f16.f16.f32 "
        "{%0,%1,%2,%3}, {%4,%5,%6,%7}, {%8,%9}, {%0,%1,%2,%3};"
        : "+f"(c[0]), "+f"(c[1]), "+f"(c[2]), "+f"(c[3])
        : "r"(a[0]), "r"(a[1]), "r"(a[2]), "r"(a[3]), "r"(b0), "r"(b1));
}
__device__ __forceinline__ void ldmat4(uint32_t* r, uint32_t addr) {
    asm volatile(
        "ldmatrix.sync.aligned.m8n8.x4.shared.b16 {%0,%1,%2,%3}, [%4];"
        : "=r"(r[0]), "=r"(r[1]), "=r"(r[2]), "=r"(r[3]) : "r"(addr));
}
__device__ __forceinline__ uint32_t packh2(float lo, float hi) {
    __half2 h = __floats2half2_rn(lo, hi);
    return *reinterpret_cast<uint32_t*>(&h);
}

// ---------------------------------------------------------------------------
// fused prep + in2f (y stored fp16); bf1 folded into k=25 of w1 table
// ---------------------------------------------------------------------------
__global__ void prep_in2f_kernel(const float* __restrict__ x,
                                 const float* __restrict__ Win,
                                 const float* __restrict__ Wf1,
                                 const float* __restrict__ Wf2,
                                 const float* __restrict__ bf1) {
    if (blockIdx.x < 256) {
        __shared__ float xs[4][NF];
        const int row4 = blockIdx.x * 4;
        for (int i = threadIdx.x; i < 4 * NF; i += 256)
            xs[i >> 7][i & 127] = x[(row4 + (i >> 7)) * NF + (i & 127)];
        __syncthreads();
        const int sub = threadIdx.x >> 6;
        const int f0 = (threadIdx.x & 63) * 2;
        float a0 = 0.0f, a1 = 0.0f;
#pragma unroll 8
        for (int i = 0; i < NF; ++i) {
            a0 += xs[sub][i] * Win[i * NF + f0];
            a1 += xs[sub][i] * Win[i * NF + f0 + 1];
        }
        g_y2[((row4 + sub) * NF + f0) >> 1] = __floats2half2_rn(a0, a1);
    } else {
        const int idx = (blockIdx.x - 256) * 256 + threadIdx.x;
        if (idx < 2048) {
            const int ks = idx >> 10, rem = idx & 1023;
            const int lane = rem >> 5, i = rem & 31;
            const int j = i >> 1, r = i & 1;
            const int n = j * 8 + (lane >> 2);
            const int k0 = ks * 16 + r * 8 + (lane & 3) * 2;
            const float v0 = (k0 < NRBF) ? Wf1[k0 * NF + n]
                           : (k0 == NRBF ? bf1[n] : 0.0f);
            const float v1 = (k0 + 1 < NRBF) ? Wf1[(k0 + 1) * NF + n]
                           : (k0 + 1 == NRBF ? bf1[n] : 0.0f);
            const int off = (ks * 32 + lane) * 32 +
                            ((((i >> 2) ^ (lane & 7)) << 2) + (i & 3));
            g_w1ph[off] = packh2(v0, v1);
        } else if (idx < 2048 + 8192) {
            const int t = idx - 2048;
            const int ks = t >> 10, rem = t & 1023;
            const int lane = rem >> 5, i = rem & 31;
            const int j = i >> 1, r = i & 1;
            const int n = j * 8 + (lane >> 2);
            const int k0 = ks * 16 + r * 8 + (lane & 3) * 2;
            const int off = (ks * 32 + lane) * 32 +
                            ((((i >> 2) ^ (lane & 7)) << 2) + (i & 3));
            g_w2ph[off] = packh2(Wf2[k0 * NF + n], Wf2[(k0 + 1) * NF + n]);
        }
    }
}

// ---------------------------------------------------------------------------
// SMEM layout (bytes)
// ---------------------------------------------------------------------------
#define OFF_H     0          // 17408 (fp16 H)
#define OFF_W2P   17408      // 32768
#define OFF_W1P   50176      // 8192
#define OFF_RBF   58368      // 5120
#define OFF_W     63488      // 35840 (fp16 W double buffer; aliased post-loop)
#define OFF_BF2   99328      // 512
#define OFF_MASK  99840      // 512
#define OFF_NJ    100352     // 512
#define OFF_NK    100864     // 512
#define SMEM_BYTES 101376    // 99KB -> 2 blocks/SM

#define NTHREADS 256

__global__ __launch_bounds__(NTHREADS, 2)
void cfconv_mma(const float* __restrict__ r_ij,
                const float* __restrict__ pmask,
                const float* __restrict__ bf2,
                const float* __restrict__ Wout, const float* __restrict__ bout,
                const int* __restrict__ nj, const int* __restrict__ nk,
                float* __restrict__ out) {
    extern __shared__ __align__(16) char smem[];
    __half*   sHh   = (__half*)(smem + OFF_H);
    uint32_t* sW2p  = (uint32_t*)(smem + OFF_W2P);
    uint32_t* sW1p  = (uint32_t*)(smem + OFF_W1P);
    __half*   sRbfH = (__half*)(smem + OFF_RBF);
    __half*   sWh   = (__half*)(smem + OFF_W);
    float* sBf2  = (float*)(smem + OFF_BF2);
    float* sMask = (float*)(smem + OFF_MASK);
    int*   sNj   = (int*)(smem + OFF_NJ);
    int*   sNk   = (int*)(smem + OFF_NK);
    float* sPart = (float*)(smem + OFF_W);
    float* sY    = (float*)(smem + OFF_W + 4096);
    float* sRed  = (float*)(smem + OFF_W + 4608);

    const int tid  = threadIdx.x;
    const int wid  = tid >> 5;
    const int lane = tid & 31;
    const int gid  = lane >> 2;
    const int l4   = lane & 3;
    const int wm   = wid >> 2;
    const int wn   = wid & 3;
    const int mbase = wm * 32;
    const int nb4   = wn * 2;
    const int f4    = lane * 4;
    const int a = blockIdx.x, b = blockIdx.y;
    const int ba = b * AA + a;
    const __half* Yb = (const __half*)g_y2 + (long)b * AA * NF;

    // division-free staging map
    const int st_t  = tid >> 2;
    const int st_r0 = (tid & 3) * 7;

    const int lrow  = (lane & 7) + ((lane >> 3) & 1) * 8;
    const int lkh   = ((lane >> 4) & 1) * 8;
    uint32_t addrR[2], addrH[2];
#pragma unroll
    for (int mt = 0; mt < 2; ++mt) {
        addrR[mt] = smem_u32(sRbfH + (mbase + mt * 16 + lrow) * RSH + lkh);
        addrH[mt] = smem_u32(sHh + (mbase + mt * 16 + lrow) * HSH + lkh);
    }

    // ---- prologue: copy W2 + W1 tables, zero rbf, bias ----
    {
        const uint4* src2 = (const uint4*)g_w2ph;
        uint4* dst2 = (uint4*)sW2p;
        for (int i = tid; i < 2048; i += NTHREADS) dst2[i] = src2[i];
        const uint4* src1 = (const uint4*)g_w1ph;
        uint4* dst1 = (uint4*)sW1p;
        for (int i = tid; i < 512; i += NTHREADS) dst1[i] = src1[i];
    }
    {
        uint32_t* z = (uint32_t*)sRbfH;
        for (int i = tid; i < (TILT * RSH) / 2; i += NTHREADS) z[i] = 0u;
    }
    if (tid < NF) sBf2[tid] = bf2[tid];
    __syncthreads();      // rbf zeros visible
    {   // bias column (k=25 of rbf = 1.0) + stage tile 0 (div-free map)
        if (tid < TILT) sRbfH[tid * RSH + NRBF] = __float2half_rn(1.0f);
        const float* rsrc = r_ij + (long)ba * TT * NRBF + st_t * NRBF;
#pragma unroll
        for (int q = 0; q < 7; ++q) {
            const int r = st_r0 + q;
            if (r < NRBF) sRbfH[st_t * RSH + r] = __float2half_rn(rsrc[r]);
        }
        if (tid < TILT) {
            const long p = (long)ba * TT + tid;
            sMask[tid] = pmask[p];
            sNj[tid] = nj[p];
            sNk[tid] = nk[p];
        }
    }
    __syncthreads();

    float4 acc0 = make_float4(0.f, 0.f, 0.f, 0.f);
    float4 acc1 = make_float4(0.f, 0.f, 0.f, 0.f);

    for (int tile = 0; tile < NTIL; ++tile) {
        const int cur = tile & 1;
        const int nxt = cur ^ 1;

        float C[2][4][4];
#pragma unroll
        for (int mt = 0; mt < 2; ++mt)
#pragma unroll
            for (int j = 0; j < 4; ++j)
#pragma unroll
                for (int q = 0; q < 4; ++q) C[mt][j][q] = 0.0f;

        // ---- GEMM1 (B-fragments from smem table) ----
#pragma unroll
        for (int ks = 0; ks < 2; ++ks) {
            uint32_t A[2][4];
            ldmat4(A[0], addrR[0] + ks * 32);
            ldmat4(A[1], addrR[1] + ks * 32);
            const uint4* rowp = (const uint4*)sW1p + (ks * 32 + lane) * 8;
            uint4 q0 = rowp[nb4 ^ (lane & 7)];
            uint4 q1 = rowp[(nb4 + 1) ^ (lane & 7)];
            uint32_t bu[8] = {q0.x, q0.y, q0.z, q0.w, q1.x, q1.y, q1.z, q1.w};
#pragma unroll
            for (int mt = 0; mt < 2; ++mt)
#pragma unroll
                for (int j = 0; j < 4; ++j)
                    mma16(C[mt][j], A[mt], bu[2 * j], bu[2 * j + 1]);
        }

        // ---- ssp (fp32 poly) -> sH ----
#pragma unroll
        for (int mt = 0; mt < 2; ++mt)
#pragma unroll
            for (int j = 0; j < 4; ++j) {
                const int f0 = wn * 32 + j * 8 + l4 * 2;
                const int r0 = mbase + mt * 16 + gid;
                *(__half2*)(sHh + r0 * HSH + f0) = ssp2(C[mt][j][0], C[mt][j][1]);
                *(__half2*)(sHh + (r0 + 8) * HSH + f0) = ssp2(C[mt][j][2], C[mt][j][3]);
            }

        // ---- prefetch next rbf tile into registers (div-free map) ----
        float rstg[7];
        float stg_mk = 0.0f; int stg_j = 0, stg_k = 0;
        if (tile < NTIL - 1) {
            const float* rnext = r_ij + ((long)ba * TT + (tile + 1) * TILT) * NRBF
                                 + st_t * NRBF;
#pragma unroll
            for (int q = 0; q < 7; ++q) {
                const int r = st_r0 + q;
                if (r < NRBF) rstg[q] = rnext[r];
            }
            if (tid < TILT) {
                const long p = (long)ba * TT + (tile + 1) * TILT + tid;
                stg_mk = pmask[p];
                stg_j = nj[p];
                stg_k = nk[p];
            }
        }
        __syncthreads();   // sync1: sH visible

        // ---- prefetch y_j rows for this tile (LDGs hidden under GEMM2) ----
        uint2 yjud[8];
#pragma unroll
        for (int r = 0; r < 8; ++r) {
            const int t = wid * 8 + r;
            yjud[r] = *(const uint2*)(Yb + sNj[cur * TILT + t] * NF + f4);
        }

        // ---- GEMM2 ----
#pragma unroll
        for (int mt = 0; mt < 2; ++mt)
#pragma unroll
            for (int j = 0; j < 4; ++j)
#pragma unroll
                for (int q = 0; q < 4; ++q) C[mt][j][q] = 0.0f;
#pragma unroll
        for (int ks = 0; ks < 8; ++ks) {
            uint32_t A[2][4];
            ldmat4(A[0], addrH[0] + ks * 32);
            ldmat4(A[1], addrH[1] + ks * 32);
            const uint4* rowp = (const uint4*)sW2p + (ks * 32 + lane) * 8;
            uint4 q0 = rowp[nb4 ^ (lane & 7)];
            uint4 q1 = rowp[(nb4 + 1) ^ (lane & 7)];
            uint32_t bu[8] = {q0.x, q0.y, q0.z, q0.w, q1.x, q1.y, q1.z, q1.w};
#pragma unroll
            for (int mt = 0; mt < 2; ++mt)
#pragma unroll
                for (int j = 0; j < 4; ++j)
                    mma16(C[mt][j], A[mt], bu[2 * j], bu[2 * j + 1]);
        }

        // ---- store (C + bf2) * mask as fp16 -> W buffer[cur] ----
        {
            __half* wb = sWh + cur * WBUF;
#pragma unroll
            for (int mt = 0; mt < 2; ++mt) {
                const int t0 = mbase + mt * 16 + gid;
                const float m0 = sMask[cur * TILT + t0];
                const float m1 = sMask[cur * TILT + t0 + 8];
#pragma unroll
                for (int j = 0; j < 4; ++j) {
                    const int f0 = wn * 32 + j * 8 + l4 * 2;
                    const float2 b2 = *(const float2*)(sBf2 + f0);
                    *(__half2*)(wb + t0 * WSH + f0) =
                        __floats2half2_rn((C[mt][j][0] + b2.x) * m0,
                                          (C[mt][j][1] + b2.y) * m0);
                    *(__half2*)(wb + (t0 + 8) * WSH + f0) =
                        __floats2half2_rn((C[mt][j][2] + b2.x) * m1,
                                          (C[mt][j][3] + b2.y) * m1);
                }
            }
        }

        // ---- store staged tile (div-free map) ----
        if (tile < NTIL - 1) {
#pragma unroll
            for (int q = 0; q < 7; ++q) {
                const int r = st_r0 + q;
                if (r < NRBF) sRbfH[st_t * RSH + r] = __float2half_rn(rstg[q]);
            }
            if (tid < TILT) {
                sMask[nxt * TILT + tid] = stg_mk;
                sNj[nxt * TILT + tid] = stg_j;
                sNk[nxt * TILT + tid] = stg_k;
            }
        }
        __syncthreads();   // sync2

        // ---- epilogue: y_j already in registers; load y_k + W here ----
        {
            const __half* wb = sWh + cur * WBUF;
#pragma unroll
            for (int r = 0; r < 8; r += 2) {
#pragma unroll
                for (int h = 0; h < 2; ++h) {
                    const int t = wid * 8 + r + h;
                    const uint2 yju = yjud[r + h];
                    const uint2 yku = *(const uint2*)(Yb + sNk[cur * TILT + t] * NF + f4);
                    const float2 ja = __half22float2(*(const __half2*)&yju.x);
                    const float2 jb = __half22float2(*(const __half2*)&yju.y);
                    const float2 ka = __half22float2(*(const __half2*)&yku.x);
                    const float2 kb = __half22float2(*(const __half2*)&yku.y);
                    const uint2 wu = *(const uint2*)(wb + t * WSH + f4);
                    const float2 wlo = __half22float2(*(const __half2*)&wu.x);
                    const float2 whi = __half22float2(*(const __half2*)&wu.y);
                    float4& av = h ? acc1 : acc0;
                    av.x = fmaf(wlo.x, ja.x * ka.x, av.x);
                    av.y = fmaf(wlo.y, ja.y * ka.y, av.y);
                    av.z = fmaf(whi.x, jb.x * kb.x, av.z);
                    av.w = fmaf(whi.y, jb.y * kb.y, av.w);
                }
            }
        }
    }

    __syncthreads();
    // ---- cross-warp reduce ----
    {
        float4 accv = make_float4(acc0.x + acc1.x, acc0.y + acc1.y,
                                  acc0.z + acc1.z, acc0.w + acc1.w);
        *(float4*)(sPart + wid * NF + f4) = accv;
    }
    __syncthreads();
    if (tid < NF) {
        float s = 0.0f;
#pragma unroll
        for (int w = 0; w < 8; ++w) s += sPart[w * NF + tid];
        sY[tid] = s;
    }
    __syncthreads();

    // ---- f2out ----
    {
        const int o = tid & 127;
        const int q = tid >> 7;
        float s = 0.0f;
        const float* Wp = Wout + q * 64 * NF + o;
#pragma unroll 8
        for (int f = 0; f < 64; ++f) s += sY[q * 64 + f] * Wp[f * NF];
        sRed[q * NF + o] = s;
    }
    __syncthreads();
    if (tid < NF)
        out[(long)ba * NF + tid] = ssp(sRed[tid] + sRed[NF + tid] + bout[tid]);
}

// ---------------------------------------------------------------------------
extern "C" void kernel_launch(void* const* d_in, const int* in_sizes, int n_in,
                              void* d_out, int out_size) {
    const float* x    = (const float*)d_in[0];
    const float* r_ij = (const float*)d_in[1];
    const float* mask = (const float*)d_in[2];
    const float* Wf1  = (const float*)d_in[3];
    const float* bf1  = (const float*)d_in[4];
    const float* Wf2  = (const float*)d_in[5];
    const float* bf2  = (const float*)d_in[6];
    const float* Win  = (const float*)d_in[7];
    const float* Wout = (const float*)d_in[8];
    const float* bout = (const float*)d_in[9];
    const int*   nj   = (const int*)d_in[10];
    const int*   nk   = (const int*)d_in[11];
    float* out = (float*)d_out;

    prep_in2f_kernel<<<296, 256>>>(x, Win, Wf1, Wf2, bf1);

    cudaFuncSetAttribute(cfconv_mma,
                         cudaFuncAttributeMaxDynamicSharedMemorySize, SMEM_BYTES);
    dim3 grid(AA, BB);
    cfconv_mma<<<grid, NTHREADS, SMEM_BYTES>>>(r_ij, mask, bf2,
                                               Wout, bout, nj, nk, out);
}

// round 14
// speedup vs baseline: 1.0541x; 1.0479x over previous
#include <cuda_runtime.h>
#include <cuda_fp16.h>
#include <cstdint>

#define BB   2
#define AA   512
#define TT   512
#define NF   128
#define NRBF 25
#define TILT 128          // block t-tile
#define NTIL (TT / TILT)  // 4
#define WPT  16           // t-rows per warp (warp-private)

#define RSH 40    // sRbf row stride (halves): conflict-free ldmatrix
#define WSH 136   // sW   row stride (halves): conflict-free frag stores

__device__ __half2  g_y2[BB * AA * NF / 2];
__device__ uint32_t g_w1ph[2 * 32 * 32];   // fp16 Wf1 B-frags (K->32, bf1 @ k=25)
__device__ uint32_t g_w2ph[8 * 32 * 32];   // fp16 Wf2 B-frags

// fp32 shifted softplus (deg-4 economized poly, |err|~6e-5)
__device__ __forceinline__ float ssp(float v) {
    const float m = fmaxf(v, 0.0f);
    const float u = __expf(-fabsf(v));
    const float x = fmaf(2.0f, u, -1.0f);
    float p = -0.00342936f;
    p = fmaf(p, x, 0.01337449f);
    p = fmaf(p, x, -0.05542695f);
    p = fmaf(p, x, 0.33307613f);
    p = fmaf(p, x, -0.28768922f);   // 0.40545796 - ln2
    return m + p;
}
__device__ __forceinline__ uint32_t smem_u32(const void* p) {
    uint32_t a;
    asm("{ .reg .u64 t; cvta.to.shared.u64 t, %1; cvt.u32.u64 %0, t; }"
        : "=r"(a) : "l"(p));
    return a;
}
__device__ __forceinline__ void mma16(float* c, const uint32_t* a,
                                      uint32_t b0, uint32_t b1) {
    asm volatile(
        "mma.sync.aligned.m16n8k16.row.col.f32.f16.f16.f32 "
        "{%0,%1,%2,%3}, {%4,%5,%6,%7}, {%8,%9}, {%0,%1,%2,%3};"
        : "+f"(c[0]), "+f"(c[1]), "+f"(c[2]), "+f"(c[3])
        : "r"(a[0]), "r"(a[1]), "r"(a[2]), "r"(a[3]), "r"(b0), "r"(b1));
}
__device__ __forceinline__ void ldmat4(uint32_t* r, uint32_t addr) {
    asm volatile(
        "ldmatrix.sync.aligned.m8n8.x4.shared.b16 {%0,%1,%2,%3}, [%4];"
        : "=r"(r[0]), "=r"(r[1]), "=r"(r[2]), "=r"(r[3]) : "r"(addr));
}
__device__ __forceinline__ uint32_t packh2(float lo, float hi) {
    __half2 h = __floats2half2_rn(lo, hi);
    return *reinterpret_cast<uint32_t*>(&h);
}

// ---------------------------------------------------------------------------
// fused prep + in2f (y stored fp16); bf1 folded into k=25 of w1 table
// ---------------------------------------------------------------------------
__global__ void prep_in2f_kernel(const float* __restrict__ x,
                                 const float* __restrict__ Win,
                                 const float* __restrict__ Wf1,
                                 const float* __restrict__ Wf2,
                                 const float* __restrict__ bf1) {
    if (blockIdx.x < 256) {
        __shared__ float xs[4][NF];
        const int row4 = blockIdx.x * 4;
        for (int i = threadIdx.x; i < 4 * NF; i += 256)
            xs[i >> 7][i & 127] = x[(row4 + (i >> 7)) * NF + (i & 127)];
        __syncthreads();
        const int sub = threadIdx.x >> 6;
        const int f0 = (threadIdx.x & 63) * 2;
        float a0 = 0.0f, a1 = 0.0f;
#pragma unroll 8
        for (int i = 0; i < NF; ++i) {
            a0 += xs[sub][i] * Win[i * NF + f0];
            a1 += xs[sub][i] * Win[i * NF + f0 + 1];
        }
        g_y2[((row4 + sub) * NF + f0) >> 1] = __floats2half2_rn(a0, a1);
    } else {
        const int idx = (blockIdx.x - 256) * 256 + threadIdx.x;
        if (idx < 2048) {
            const int ks = idx >> 10, rem = idx & 1023;
            const int lane = rem >> 5, i = rem & 31;
            const int j = i >> 1, r = i & 1;
            const int n = j * 8 + (lane >> 2);
            const int k0 = ks * 16 + r * 8 + (lane & 3) * 2;
            const float v0 = (k0 < NRBF) ? Wf1[k0 * NF + n]
                           : (k0 == NRBF ? bf1[n] : 0.0f);
            const float v1 = (k0 + 1 < NRBF) ? Wf1[(k0 + 1) * NF + n]
                           : (k0 + 1 == NRBF ? bf1[n] : 0.0f);
            const int off = (ks * 32 + lane) * 32 +
                            ((((i >> 2) ^ (lane & 7)) << 2) + (i & 3));
            g_w1ph[off] = packh2(v0, v1);
        } else if (idx < 2048 + 8192) {
            const int t = idx - 2048;
            const int ks = t >> 10, rem = t & 1023;
            const int lane = rem >> 5, i = rem & 31;
            const int j = i >> 1, r = i & 1;
            const int n = j * 8 + (lane >> 2);
            const int k0 = ks * 16 + r * 8 + (lane & 3) * 2;
            const int off = (ks * 32 + lane) * 32 +
                            ((((i >> 2) ^ (lane & 7)) << 2) + (i & 3));
            g_w2ph[off] = packh2(Wf2[k0 * NF + n], Wf2[(k0 + 1) * NF + n]);
        }
    }
}

// ---------------------------------------------------------------------------
// SMEM layout (bytes)
// ---------------------------------------------------------------------------
#define OFF_W2P   0          // 32768
#define OFF_W1P   32768      // 8192
#define OFF_RBF   40960      // 128*40*2 = 10240
#define OFF_W     51200      // 128*136*2 = 34816 (aliased post-loop)
#define OFF_BF2   86016      // 512
#define OFF_MASK  86528      // 512
#define OFF_NJ    87040      // 512
#define OFF_NK    87552      // 512
#define SMEM_BYTES 88064     // 86KB -> 2 blocks/SM

#define NTHREADS 256

__global__ __launch_bounds__(NTHREADS, 2)
void cfconv_mma(const float* __restrict__ r_ij,
                const float* __restrict__ pmask,
                const float* __restrict__ bf2,
                const float* __restrict__ Wout, const float* __restrict__ bout,
                const int* __restrict__ nj, const int* __restrict__ nk,
                float* __restrict__ out) {
    extern __shared__ __align__(16) char smem[];
    uint32_t* sW2p  = (uint32_t*)(smem + OFF_W2P);
    uint32_t* sW1p  = (uint32_t*)(smem + OFF_W1P);
    __half*   sRbfH = (__half*)(smem + OFF_RBF);
    __half*   sWh   = (__half*)(smem + OFF_W);
    float* sBf2  = (float*)(smem + OFF_BF2);
    float* sMask = (float*)(smem + OFF_MASK);
    int*   sNj   = (int*)(smem + OFF_NJ);
    int*   sNk   = (int*)(smem + OFF_NK);
    float* sPart = (float*)(smem + OFF_W);
    float* sY    = (float*)(smem + OFF_W + 4096);
    float* sRed  = (float*)(smem + OFF_W + 4608);

    const int tid  = threadIdx.x;
    const int wid  = tid >> 5;
    const int lane = tid & 31;
    const int gid  = lane >> 2;
    const int l4   = lane & 3;
    const int wt0  = wid * WPT;       // warp's t-row base within 128-row tile
    const int f4   = lane * 4;        // epilogue f-ownership
    const int a = blockIdx.x, b = blockIdx.y;
    const int ba = b * AA + a;
    const __half* Yb = (const __half*)g_y2 + (long)b * AA * NF;

    // warp-local rbf staging: lane pair covers one row (cols 0-12 / 13-24)
    const int srow = wt0 + (lane >> 1);
    const int scol = (lane & 1) * 13;
    const int scnt = (lane & 1) ? 12 : 13;

    // ldmatrix addressing for rbf A-fragments (own 16 rows)
    const int lrow = (lane & 7) + ((lane >> 3) & 1) * 8;
    const int lkh  = ((lane >> 4) & 1) * 8;
    const uint32_t addrR = smem_u32(sRbfH + (wt0 + lrow) * RSH + lkh);

    // ---- prologue ----
    {
        const uint4* src2 = (const uint4*)g_w2ph;
        uint4* dst2 = (uint4*)sW2p;
        for (int i = tid; i < 2048; i += NTHREADS) dst2[i] = src2[i];
        const uint4* src1 = (const uint4*)g_w1ph;
        uint4* dst1 = (uint4*)sW1p;
        for (int i = tid; i < 512; i += NTHREADS) dst1[i] = src1[i];
    }
    {
        uint32_t* z = (uint32_t*)sRbfH;
        for (int i = tid; i < (TILT * RSH) / 2; i += NTHREADS) z[i] = 0u;
    }
    if (tid < NF) sBf2[tid] = bf2[tid];
    __syncthreads();
    // bias column (k=25 == 1.0) for own warp rows (warp-local; syncwarp below covers)
    if (lane < WPT) sRbfH[(wt0 + lane) * RSH + NRBF] = __float2half_rn(1.0f);

    float4 acc0 = make_float4(0.f, 0.f, 0.f, 0.f);
    float4 acc1 = make_float4(0.f, 0.f, 0.f, 0.f);
    float C2[64];

    for (int tile = 0; tile < NTIL; ++tile) {
        // ---- warp-local staging of own 16 rows ----
        {
            const long tg = (long)ba * TT + tile * TILT;
            const float* rs = r_ij + (tg + srow) * NRBF + scol;
#pragma unroll
            for (int q = 0; q < 13; ++q)
                if (q < scnt) sRbfH[srow * RSH + scol + q] = __float2half_rn(rs[q]);
            if (lane < WPT) {
                const int t = wt0 + lane;
                const long p = tg + t;
                sMask[t] = pmask[p];
                sNj[t] = nj[p];
                sNk[t] = nk[p];
            }
        }
        __syncwarp();

        // rbf A-fragments (K=32, tile-constant across g-chunks)
        uint32_t Ar0[4], Ar1[4];
        ldmat4(Ar0, addrR);
        ldmat4(Ar1, addrR + 32);

#pragma unroll
        for (int i = 0; i < 64; ++i) C2[i] = 0.0f;

        // ---- fused GEMM1 -> ssp -> GEMM2, per 16-g chunk, register-only ----
#pragma unroll
        for (int gc = 0; gc < 8; ++gc) {
            const uint4* r0 = (const uint4*)sW1p + lane * 8;
            const uint4* r1 = (const uint4*)sW1p + (32 + lane) * 8;
            const uint4 q0 = r0[gc ^ (lane & 7)];
            const uint4 q1 = r1[gc ^ (lane & 7)];
            float C1[8] = {0.f, 0.f, 0.f, 0.f, 0.f, 0.f, 0.f, 0.f};
            mma16(C1,     Ar0, q0.x, q0.y);     // j = 2gc,   k 0-15
            mma16(C1 + 4, Ar0, q0.z, q0.w);     // j = 2gc+1
            mma16(C1,     Ar1, q1.x, q1.y);     // k 16-31
            mma16(C1 + 4, Ar1, q1.z, q1.w);
            // accumulator frag -> ssp -> A-operand frag (exact layout match)
            uint32_t A2[4];
            A2[0] = packh2(ssp(C1[0]), ssp(C1[1]));   // row gid,   k l4*2
            A2[1] = packh2(ssp(C1[2]), ssp(C1[3]));   // row gid+8, k l4*2
            A2[2] = packh2(ssp(C1[4]), ssp(C1[5]));   // row gid,   k 8+l4*2
            A2[3] = packh2(ssp(C1[6]), ssp(C1[7]));   // row gid+8, k 8+l4*2
            const uint4* r2 = (const uint4*)sW2p + (gc * 32 + lane) * 8;
#pragma unroll
            for (int jg = 0; jg < 8; ++jg) {
                const uint4 q = r2[jg ^ (lane & 7)];
                mma16(C2 + jg * 8,     A2, q.x, q.y);
                mma16(C2 + jg * 8 + 4, A2, q.z, q.w);
            }
        }

        // ---- store (C2 + bf2) * mask as fp16 into warp-private W rows ----
        {
            const float m0 = sMask[wt0 + gid];
            const float m1 = sMask[wt0 + gid + 8];
            __half* wr0 = sWh + (wt0 + gid) * WSH;
            __half* wr1 = sWh + (wt0 + gid + 8) * WSH;
#pragma unroll
            for (int j = 0; j < 16; ++j) {
                const int f0 = j * 8 + l4 * 2;
                const float2 b2 = *(const float2*)(sBf2 + f0);
                *(__half2*)(wr0 + f0) =
                    __floats2half2_rn((C2[j * 4 + 0] + b2.x) * m0,
                                      (C2[j * 4 + 1] + b2.y) * m0);
                *(__half2*)(wr1 + f0) =
                    __floats2half2_rn((C2[j * 4 + 2] + b2.x) * m1,
                                      (C2[j * 4 + 3] + b2.y) * m1);
            }
        }
        __syncwarp();

        // ---- row-coalesced gather epilogue over own 16 rows ----
#pragma unroll
        for (int r = 0; r < WPT; r += 2) {
#pragma unroll
            for (int h = 0; h < 2; ++h) {
                const int t = wt0 + r + h;
                const uint2 yju = *(const uint2*)(Yb + sNj[t] * NF + f4);
                const uint2 yku = *(const uint2*)(Yb + sNk[t] * NF + f4);
                const uint2 wu  = *(const uint2*)(sWh + t * WSH + f4);
                const float2 ja = __half22float2(*(const __half2*)&yju.x);
                const float2 jb = __half22float2(*(const __half2*)&yju.y);
                const float2 ka = __half22float2(*(const __half2*)&yku.x);
                const float2 kb = __half22float2(*(const __half2*)&yku.y);
                const float2 wlo = __half22float2(*(const __half2*)&wu.x);
                const float2 whi = __half22float2(*(const __half2*)&wu.y);
                float4& av = h ? acc1 : acc0;
                av.x = fmaf(wlo.x, ja.x * ka.x, av.x);
                av.y = fmaf(wlo.y, ja.y * ka.y, av.y);
                av.z = fmaf(whi.x, jb.x * kb.x, av.z);
                av.w = fmaf(whi.y, jb.y * kb.y, av.w);
            }
        }
        __syncwarp();   // epilogue reads done before next tile's staging overwrites
    }

    __syncthreads();    // all warps done before aliasing W region
    // ---- cross-warp reduce (warp x f4 partitions are disjoint per warp) ----
    {
        float4 accv = make_float4(acc0.x + acc1.x, acc0.y + acc1.y,
                                  acc0.z + acc1.z, acc0.w + acc1.w);
        *(float4*)(sPart + wid * NF + f4) = accv;
    }
    __syncthreads();
    if (tid < NF) {
        float s = 0.0f;
#pragma unroll
        for (int w = 0; w < 8; ++w) s += sPart[w * NF + tid];
        sY[tid] = s;
    }
    __syncthreads();

    // ---- f2out: out = ssp(y @ Wout + bout) ----
    {
        const int o = tid & 127;
        const int q = tid >> 7;
        float s = 0.0f;
        const float* Wp = Wout + q * 64 * NF + o;
#pragma unroll 8
        for (int f = 0; f < 64; ++f) s += sY[q * 64 + f] * Wp[f * NF];
        sRed[q * NF + o] = s;
    }
    __syncthreads();
    if (tid < NF)
        out[(long)ba * NF + tid] = ssp(sRed[tid] + sRed[NF + tid] + bout[tid]);
}

// ---------------------------------------------------------------------------
extern "C" void kernel_launch(void* const* d_in, const int* in_sizes, int n_in,
                              void* d_out, int out_size) {
    const float* x    = (const float*)d_in[0];
    const float* r_ij = (const float*)d_in[1];
    const float* mask = (const float*)d_in[2];
    const float* Wf1  = (const float*)d_in[3];
    const float* bf1  = (const float*)d_in[4];
    const float* Wf2  = (const float*)d_in[5];
    const float* bf2  = (const float*)d_in[6];
    const float* Win  = (const float*)d_in[7];
    const float* Wout = (const float*)d_in[8];
    const float* bout = (const float*)d_in[9];
    const int*   nj   = (const int*)d_in[10];
    const int*   nk   = (const int*)d_in[11];
    float* out = (float*)d_out;

    prep_in2f_kernel<<<296, 256>>>(x, Win, Wf1, Wf2, bf1);

    cudaFuncSetAttribute(cfconv_mma,
                         cudaFuncAttributeMaxDynamicSharedMemorySize, SMEM_BYTES);
    dim3 grid(AA, BB);
    cfconv_mma<<<grid, NTHREADS, SMEM_BYTES>>>(r_ij, mask, bf2,
                                               Wout, bout, nj, nk, out);
}

// round 15
// speedup vs baseline: 1.1066x; 1.0498x over previous
#include <cuda_runtime.h>
#include <cuda_fp16.h>
#include <cstdint>

#define BB   2
#define AA   512
#define TT   512
#define NF   128
#define NRBF 25
#define TILT 64           // block t-tile: 4 pairs x 16 rows
#define NTIL (TT / TILT)  // 8
#define PRB  4352         // pair region bytes (aliased rbf/A2/W)

__device__ __half2  g_y2[BB * AA * NF / 2];
__device__ uint32_t g_w1ph[2 * 32 * 32];   // 8KB  fp16 Wf1 B-frags (bf1 @ k=25)
__device__ uint32_t g_w2ph[8 * 32 * 32];   // 32KB fp16 Wf2 B-frags

__device__ __forceinline__ float ssp(float v) {
    const float m = fmaxf(v, 0.0f);
    const float u = __expf(-fabsf(v));
    const float x = fmaf(2.0f, u, -1.0f);
    float p = -0.00342936f;
    p = fmaf(p, x, 0.01337449f);
    p = fmaf(p, x, -0.05542695f);
    p = fmaf(p, x, 0.33307613f);
    p = fmaf(p, x, -0.28768922f);   // 0.40545796 - ln2
    return m + p;
}
__device__ __forceinline__ uint32_t smem_u32(const void* p) {
    uint32_t a;
    asm("{ .reg .u64 t; cvta.to.shared.u64 t, %1; cvt.u32.u64 %0, t; }"
        : "=r"(a) : "l"(p));
    return a;
}
__device__ __forceinline__ void mma16(float* c, const uint32_t* a,
                                      uint32_t b0, uint32_t b1) {
    asm volatile(
        "mma.sync.aligned.m16n8k16.row.col.f32.f16.f16.f32 "
        "{%0,%1,%2,%3}, {%4,%5,%6,%7}, {%8,%9}, {%0,%1,%2,%3};"
        : "+f"(c[0]), "+f"(c[1]), "+f"(c[2]), "+f"(c[3])
        : "r"(a[0]), "r"(a[1]), "r"(a[2]), "r"(a[3]), "r"(b0), "r"(b1));
}
__device__ __forceinline__ void ldmat4(uint32_t* r, uint32_t addr) {
    asm volatile(
        "ldmatrix.sync.aligned.m8n8.x4.shared.b16 {%0,%1,%2,%3}, [%4];"
        : "=r"(r[0]), "=r"(r[1]), "=r"(r[2]), "=r"(r[3]) : "r"(addr));
}
__device__ __forceinline__ uint32_t packh2(float lo, float hi) {
    __half2 h = __floats2half2_rn(lo, hi);
    return *reinterpret_cast<uint32_t*>(&h);
}
#define PBAR(id) asm volatile("bar.sync %0, 64;" :: "r"(id) : "memory")

// ---------------------------------------------------------------------------
// fused prep + in2f (y fp16); bf1 folded into k=25 of w1 table
// ---------------------------------------------------------------------------
__global__ void prep_in2f_kernel(const float* __restrict__ x,
                                 const float* __restrict__ Win,
                                 const float* __restrict__ Wf1,
                                 const float* __restrict__ Wf2,
                                 const float* __restrict__ bf1) {
    if (blockIdx.x < 256) {
        __shared__ float xs[4][NF];
        const int row4 = blockIdx.x * 4;
        for (int i = threadIdx.x; i < 4 * NF; i += 256)
            xs[i >> 7][i & 127] = x[(row4 + (i >> 7)) * NF + (i & 127)];
        __syncthreads();
        const int sub = threadIdx.x >> 6;
        const int f0 = (threadIdx.x & 63) * 2;
        float a0 = 0.0f, a1 = 0.0f;
#pragma unroll 8
        for (int i = 0; i < NF; ++i) {
            a0 += xs[sub][i] * Win[i * NF + f0];
            a1 += xs[sub][i] * Win[i * NF + f0 + 1];
        }
        g_y2[((row4 + sub) * NF + f0) >> 1] = __floats2half2_rn(a0, a1);
    } else {
        const int idx = (blockIdx.x - 256) * 256 + threadIdx.x;
        if (idx < 2048) {
            const int ks = idx >> 10, rem = idx & 1023;
            const int lane = rem >> 5, i = rem & 31;
            const int j = i >> 1, r = i & 1;
            const int n = j * 8 + (lane >> 2);
            const int k0 = ks * 16 + r * 8 + (lane & 3) * 2;
            const float v0 = (k0 < NRBF) ? Wf1[k0 * NF + n]
                           : (k0 == NRBF ? bf1[n] : 0.0f);
            const float v1 = (k0 + 1 < NRBF) ? Wf1[(k0 + 1) * NF + n]
                           : (k0 + 1 == NRBF ? bf1[n] : 0.0f);
            const int off = (ks * 32 + lane) * 32 +
                            ((((i >> 2) ^ (lane & 7)) << 2) + (i & 3));
            g_w1ph[off] = packh2(v0, v1);
        } else if (idx < 2048 + 8192) {
            const int t = idx - 2048;
            const int ks = t >> 10, rem = t & 1023;
            const int lane = rem >> 5, i = rem & 31;
            const int j = i >> 1, r = i & 1;
            const int n = j * 8 + (lane >> 2);
            const int k0 = ks * 16 + r * 8 + (lane & 3) * 2;
            const int off = (ks * 32 + lane) * 32 +
                            ((((i >> 2) ^ (lane & 7)) << 2) + (i & 3));
            g_w2ph[off] = packh2(Wf2[k0 * NF + n], Wf2[(k0 + 1) * NF + n]);
        }
    }
}

// ---------------------------------------------------------------------------
// SMEM layout (bytes)
// ---------------------------------------------------------------------------
#define OFF_W2P   0          // 32768
#define OFF_W1P   32768      // 8192
#define OFF_PB    40960      // 4 pairs x 4352 = 17408 (rbf/A2/W aliased)
#define OFF_BF2   58368      // 512
#define OFF_MASK  58880      // 256 (64 floats)
#define OFF_NJ    59136      // 256
#define OFF_NK    59392      // 256
#define SMEM_BYTES 59648     // 58.25KB -> 3 blocks/SM

#define NTHREADS 256

__global__ __launch_bounds__(NTHREADS, 3)
void cfconv_mma(const float* __restrict__ r_ij,
                const float* __restrict__ pmask,
                const float* __restrict__ bf2,
                const float* __restrict__ Wout, const float* __restrict__ bout,
                const int* __restrict__ nj, const int* __restrict__ nk,
                float* __restrict__ out) {
    extern __shared__ __align__(16) char smem[];
    uint32_t* sW2p  = (uint32_t*)(smem + OFF_W2P);
    uint32_t* sW1p  = (uint32_t*)(smem + OFF_W1P);
    float* sBf2  = (float*)(smem + OFF_BF2);
    float* sMask = (float*)(smem + OFF_MASK);
    int*   sNj   = (int*)(smem + OFF_NJ);
    int*   sNk   = (int*)(smem + OFF_NK);
    float* sPart = (float*)(smem + OFF_PB);            // post-loop aliases
    float* sY    = (float*)(smem + OFF_PB + 4096);
    float* sRed  = (float*)(smem + OFF_PB + 4608);

    const int tid  = threadIdx.x;
    const int wid  = tid >> 5;
    const int lane = tid & 31;
    const int gid  = lane >> 2;
    const int l4   = lane & 3;
    const int pair = wid >> 1;        // 0..3
    const int h    = wid & 1;         // k-half in GEMM1, f-half in GEMM2
    const int f4   = lane * 4;
    const int a = blockIdx.x, b = blockIdx.y;
    const int ba = b * AA + a;
    const __half* Yb = (const __half*)g_y2 + (long)b * AA * NF;

    char* pb = smem + OFF_PB + pair * PRB;
    __half* pH = (__half*)pb;          // rbf rows r*40h / W rows r*136h (aliased)
    const uint32_t pbu = smem_u32(pb);
    const int barid = pair + 1;

    // staging map: warp h covers rows [8h, 8h+8); 4 lanes per row, 8 cols each
    const int srow = (h << 3) + (lane >> 2);
    const int scol = (lane & 3) * 8;

    // ldmatrix map (rows 0..15 of pair)
    const int lrow = (lane & 7) + ((lane >> 3) & 1) * 8;
    const int lkh  = ((lane >> 4) & 1) * 8;
    const uint32_t addrR = pbu + (uint32_t)(lrow * 80 + lkh * 2);

    // ---- prologue: weight tables + bf2 ----
    {
        const uint4* src2 = (const uint4*)g_w2ph;
        uint4* dst2 = (uint4*)sW2p;
        for (int i = tid; i < 2048; i += NTHREADS) dst2[i] = src2[i];
        const uint4* src1 = (const uint4*)g_w1ph;
        uint4* dst1 = (uint4*)sW1p;
        for (int i = tid; i < 512; i += NTHREADS) dst1[i] = src1[i];
    }
    if (tid < NF) sBf2[tid] = bf2[tid];
    __syncthreads();

    float4 acc0 = make_float4(0.f, 0.f, 0.f, 0.f);
    float4 acc1 = make_float4(0.f, 0.f, 0.f, 0.f);

    for (int tile = 0; tile < NTIL; ++tile) {
        // ---- stage rbf (K padded: col25=1 bias, 26..31=0) + meta ----
        {
            const long tg = (long)ba * TT + tile * TILT;
            const float* rs = r_ij + (tg + pair * 16 + srow) * NRBF;
#pragma unroll
            for (int q = 0; q < 8; ++q) {
                const int col = scol + q;
                const float v = (col < NRBF) ? rs[col]
                              : (col == NRBF ? 1.0f : 0.0f);
                pH[srow * 40 + col] = __float2half_rn(v);
            }
            if (lane < 8) {
                const int rl = (h << 3) + lane;
                const long p = tg + pair * 16 + rl;
                sMask[pair * 16 + rl] = pmask[p];
                sNj[pair * 16 + rl] = nj[p];
                sNk[pair * 16 + rl] = nk[p];
            }
        }
        PBAR(barid);                       // stage complete (both warps)

        uint32_t Ar0[4], Ar1[4];
        ldmat4(Ar0, addrR);
        ldmat4(Ar1, addrR + 32);
        PBAR(barid);                       // rbf consumed; A2 may clobber

        // ---- GEMM1 + ssp for own k-chunks gc in [4h, 4h+4) -> A2 exchange ----
#pragma unroll
        for (int g4 = 0; g4 < 4; ++g4) {
            const int gc = (h << 2) + g4;
            const uint4 q0 = ((const uint4*)sW1p + lane * 8)[gc ^ (lane & 7)];
            const uint4 q1 = ((const uint4*)sW1p + (32 + lane) * 8)[gc ^ (lane & 7)];
            float C1[8] = {0.f, 0.f, 0.f, 0.f, 0.f, 0.f, 0.f, 0.f};
            mma16(C1,     Ar0, q0.x, q0.y);
            mma16(C1 + 4, Ar0, q0.z, q0.w);
            mma16(C1,     Ar1, q1.x, q1.y);
            mma16(C1 + 4, Ar1, q1.z, q1.w);
            const uint32_t a0 = packh2(ssp(C1[0]), ssp(C1[1]));
            const uint32_t a1 = packh2(ssp(C1[2]), ssp(C1[3]));
            const uint32_t a2 = packh2(ssp(C1[4]), ssp(C1[5]));
            const uint32_t a3 = packh2(ssp(C1[6]), ssp(C1[7]));
            asm volatile("st.shared.v4.b32 [%0], {%1,%2,%3,%4};"
                :: "r"(pbu + (uint32_t)(gc * 512 + lane * 16)),
                   "r"(a0), "r"(a1), "r"(a2), "r"(a3) : "memory");
        }
        PBAR(barid);                       // all A2 frags ready

        // ---- GEMM2: all 8 gc, own f-half (N=64), C2 = 32 regs ----
        float C2[4][8];
#pragma unroll
        for (int j = 0; j < 4; ++j)
#pragma unroll
            for (int q = 0; q < 8; ++q) C2[j][q] = 0.0f;
#pragma unroll
        for (int gc = 0; gc < 8; ++gc) {
            uint32_t A2r[4];
            asm volatile("ld.shared.v4.b32 {%0,%1,%2,%3}, [%4];"
                : "=r"(A2r[0]), "=r"(A2r[1]), "=r"(A2r[2]), "=r"(A2r[3])
                : "r"(pbu + (uint32_t)(gc * 512 + lane * 16)));
            const uint4* r2 = (const uint4*)sW2p + (gc * 32 + lane) * 8;
#pragma unroll
            for (int j = 0; j < 4; ++j) {
                const uint4 q = r2[((h << 2) + j) ^ (lane & 7)];
                mma16(C2[j],     A2r, q.x, q.y);
                mma16(C2[j] + 4, A2r, q.z, q.w);
            }
        }
        PBAR(barid);                       // A2 reads done; W may clobber

        // ---- store (C2 + bf2) * mask as fp16 W rows (own f-half) ----
        {
            const float m0 = sMask[pair * 16 + gid];
            const float m1 = sMask[pair * 16 + gid + 8];
#pragma unroll
            for (int j = 0; j < 4; ++j) {
                const int f0 = (h << 6) + j * 16 + l4 * 2;
                const float2 b2a = *(const float2*)(sBf2 + f0);
                const float2 b2b = *(const float2*)(sBf2 + f0 + 8);
                *(__half2*)(pH + gid * 136 + f0) =
                    __floats2half2_rn((C2[j][0] + b2a.x) * m0,
                                      (C2[j][1] + b2a.y) * m0);
                *(__half2*)(pH + (gid + 8) * 136 + f0) =
                    __floats2half2_rn((C2[j][2] + b2a.x) * m1,
                                      (C2[j][3] + b2a.y) * m1);
                *(__half2*)(pH + gid * 136 + f0 + 8) =
                    __floats2half2_rn((C2[j][4] + b2b.x) * m0,
                                      (C2[j][5] + b2b.y) * m0);
                *(__half2*)(pH + (gid + 8) * 136 + f0 + 8) =
                    __floats2half2_rn((C2[j][6] + b2b.x) * m1,
                                      (C2[j][7] + b2b.y) * m1);
            }
        }
        PBAR(barid);                       // W complete (both halves)

        // ---- row-coalesced gather epilogue over own 8 rows ----
#pragma unroll
        for (int rr = 0; rr < 8; rr += 2) {
#pragma unroll
            for (int hh = 0; hh < 2; ++hh) {
                const int rl = (h << 3) + rr + hh;
                const int t = pair * 16 + rl;
                const uint2 yju = *(const uint2*)(Yb + sNj[t] * NF + f4);
                const uint2 yku = *(const uint2*)(Yb + sNk[t] * NF + f4);
                const uint2 wu  = *(const uint2*)(pH + rl * 136 + f4);
                const float2 ja = __half22float2(*(const __half2*)&yju.x);
                const float2 jb = __half22float2(*(const __half2*)&yju.y);
                const float2 ka = __half22float2(*(const __half2*)&yku.x);
                const float2 kb = __half22float2(*(const __half2*)&yku.y);
                const float2 wlo = __half22float2(*(const __half2*)&wu.x);
                const float2 whi = __half22float2(*(const __half2*)&wu.y);
                float4& av = hh ? acc1 : acc0;
                av.x = fmaf(wlo.x, ja.x * ka.x, av.x);
                av.y = fmaf(wlo.y, ja.y * ka.y, av.y);
                av.z = fmaf(whi.x, jb.x * kb.x, av.z);
                av.w = fmaf(whi.y, jb.y * kb.y, av.w);
            }
        }
        PBAR(barid);                       // W reads done; next stage may clobber
    }

    __syncthreads();
    // ---- cross-warp reduce (each warp covered disjoint rows, full f) ----
    {
        float4 accv = make_float4(acc0.x + acc1.x, acc0.y + acc1.y,
                                  acc0.z + acc1.z, acc0.w + acc1.w);
        *(float4*)(sPart + wid * NF + f4) = accv;
    }
    __syncthreads();
    if (tid < NF) {
        float s = 0.0f;
#pragma unroll
        for (int w = 0; w < 8; ++w) s += sPart[w * NF + tid];
        sY[tid] = s;
    }
    __syncthreads();

    // ---- f2out: out = ssp(y @ Wout + bout) ----
    {
        const int o = tid & 127;
        const int q = tid >> 7;
        float s = 0.0f;
        const float* Wp = Wout + q * 64 * NF + o;
#pragma unroll 8
        for (int f = 0; f < 64; ++f) s += sY[q * 64 + f] * Wp[f * NF];
        sRed[q * NF + o] = s;
    }
    __syncthreads();
    if (tid < NF)
        out[(long)ba * NF + tid] = ssp(sRed[tid] + sRed[NF + tid] + bout[tid]);
}

// ---------------------------------------------------------------------------
extern "C" void kernel_launch(void* const* d_in, const int* in_sizes, int n_in,
                              void* d_out, int out_size) {
    const float* x    = (const float*)d_in[0];
    const float* r_ij = (const float*)d_in[1];
    const float* mask = (const float*)d_in[2];
    const float* Wf1  = (const float*)d_in[3];
    const float* bf1  = (const float*)d_in[4];
    const float* Wf2  = (const float*)d_in[5];
    const float* bf2  = (const float*)d_in[6];
    const float* Win  = (const float*)d_in[7];
    const float* Wout = (const float*)d_in[8];
    const float* bout = (const float*)d_in[9];
    const int*   nj   = (const int*)d_in[10];
    const int*   nk   = (const int*)d_in[11];
    float* out = (float*)d_out;

    prep_in2f_kernel<<<296, 256>>>(x, Win, Wf1, Wf2, bf1);

    cudaFuncSetAttribute(cfconv_mma,
                         cudaFuncAttributeMaxDynamicSharedMemorySize, SMEM_BYTES);
    dim3 grid(AA, BB);
    cfconv_mma<<<grid, NTHREADS, SMEM_BYTES>>>(r_ij, mask, bf2,
                                               Wout, bout, nj, nk, out);
}